// round 6
// baseline (speedup 1.0000x reference)
#include <cuda_runtime.h>
#include <cstdint>

#define HH   480
#define WW   864
#define W4   216                 // WW/4
#define HW4  (HH*W4)             // 103680 float4 per sample
#define HWX  (HH*WW)
#define MAXB 224
#define RCH  15                  // row-chunks per sample (32 rows each)
#define RPB  32                  // rows per chunk
#define NTHREADS 256
#define GRID 592                 // persistent-ish; correctness does NOT require co-residency

__device__ int      g_pcnt [MAXB][RCH];
__device__ int      g_pcmin[MAXB][RCH];
__device__ int      g_pcmax[MAXB][RCH];
__device__ unsigned g_prmask[MAXB][RCH];
__device__ int4     g_bbox[MAXB];
__device__ int      g_sdone[MAXB];   // chunks finished per sample
__device__ int      g_flag [MAXB];   // bbox ready
__device__ int      g_qred  = 0;     // reduce work queue head
__device__ int      g_qfill = 0;     // fill work queue head
__device__ int      g_exited = 0;    // last-block-out resets everything

__device__ __forceinline__ uint64_t pol_evict_first() {
    uint64_t p;
    asm("createpolicy.fractional.L2::evict_first.b64 %0, 1.0;" : "=l"(p));
    return p;
}
__device__ __forceinline__ uint64_t pol_evict_last() {
    uint64_t p;
    asm("createpolicy.fractional.L2::evict_last.b64 %0, 1.0;" : "=l"(p));
    return p;
}
__device__ __forceinline__ float4 ld_pin(const float4* a, uint64_t pol) {
    float4 v;
    asm("ld.global.nc.L2::cache_hint.v4.f32 {%0,%1,%2,%3}, [%4], %5;"
        : "=f"(v.x), "=f"(v.y), "=f"(v.z), "=f"(v.w)
        : "l"(a), "l"(pol));
    return v;
}
__device__ __forceinline__ void st_stream(float4* a, float4 v, uint64_t pol) {
    asm volatile("st.global.L2::cache_hint.v4.f32 [%0], {%1,%2,%3,%4}, %5;"
                 :: "l"(a), "f"(v.x), "f"(v.y), "f"(v.z), "f"(v.w), "l"(pol)
                 : "memory");
}

__global__ __launch_bounds__(NTHREADS) void ram_fused(const float4* __restrict__ mask,
                                                      const int* __restrict__ n_pts,
                                                      const int* __restrict__ n_loose,
                                                      float4* __restrict__ out,
                                                      float* __restrict__ out_bbox,
                                                      int B)
{
    const int t = threadIdx.x;
    const uint64_t ppin = pol_evict_last();
    const uint64_t pstr = pol_evict_first();
    const int NR = B * RCH;

    __shared__ int s_item;
    __shared__ int scnt[8], scmin[8], scmax[8];
    __shared__ unsigned srm[8];

    // ---------------- Phase 1: reduce (dynamic queue) ----------------
    for (;;) {
        if (t == 0) s_item = atomicAdd(&g_qred, 1);
        __syncthreads();
        const int item = s_item;
        if (item >= NR) break;
        const int b  = item / RCH;
        const int ch = item - b * RCH;

        float m0 = 0.f, m1 = 0.f, m2 = 0.f, m3 = 0.f;
        int cnt = 0;
        unsigned rmask = 0;

        if (t < W4) {
            const float4* p = mask + (size_t)b * HW4 + (size_t)(ch * RPB) * W4 + t;
            #pragma unroll 8
            for (int j = 0; j < RPB; j++) {
                float4 v = ld_pin(&p[(size_t)j * W4], ppin);
                m0 = fmaxf(m0, v.x); m1 = fmaxf(m1, v.y);
                m2 = fmaxf(m2, v.z); m3 = fmaxf(m3, v.w);
                cnt += (v.x > 0.5f) + (v.y > 0.5f) + (v.z > 0.5f) + (v.w > 0.5f);
                float rm = fmaxf(fmaxf(v.x, v.y), fmaxf(v.z, v.w));
                rmask |= (rm > 0.5f) ? (1u << j) : 0u;
            }
        }

        const int c = t * 4;
        int cmin = (m0 > 0.5f) ? c
                 : (m1 > 0.5f) ? c + 1
                 : (m2 > 0.5f) ? c + 2
                 : (m3 > 0.5f) ? c + 3 : (1 << 30);
        int cmax = (m3 > 0.5f) ? c + 3
                 : (m2 > 0.5f) ? c + 2
                 : (m1 > 0.5f) ? c + 1
                 : (m0 > 0.5f) ? c : -1;

        cnt   = __reduce_add_sync(0xffffffffu, cnt);
        cmin  = __reduce_min_sync(0xffffffffu, cmin);
        cmax  = __reduce_max_sync(0xffffffffu, cmax);
        rmask = __reduce_or_sync (0xffffffffu, rmask);

        const int w = t >> 5;
        if ((t & 31) == 0) { scnt[w] = cnt; scmin[w] = cmin; scmax[w] = cmax; srm[w] = rmask; }
        __syncthreads();

        if (t == 0) {
            #pragma unroll
            for (int i = 1; i < 8; i++) {
                cnt += scnt[i];
                cmin = min(cmin, scmin[i]);
                cmax = max(cmax, scmax[i]);
                rmask |= srm[i];
            }
            g_pcnt[b][ch] = cnt; g_pcmin[b][ch] = cmin;
            g_pcmax[b][ch] = cmax; g_prmask[b][ch] = rmask;
            __threadfence();
            if (atomicAdd(&g_sdone[b], 1) == RCH - 1) {
                // last chunk of sample b: finalize its bbox immediately
                __threadfence();
                int tc = 0, tcmin = 1 << 30, tcmax = -1, tminr = 1 << 30, tmaxr = -1;
                #pragma unroll
                for (int i = 0; i < RCH; i++) {
                    tc   += g_pcnt[b][i];
                    tcmin = min(tcmin, g_pcmin[b][i]);
                    tcmax = max(tcmax, g_pcmax[b][i]);
                    unsigned rm = g_prmask[b][i];
                    if (rm) {
                        tminr = min(tminr, i * RPB + (__ffs(rm) - 1));
                        tmaxr = max(tmaxr, i * RPB + (31 - __clz(rm)));
                    }
                }
                const int loose = *n_loose, thr = *n_pts;
                const bool full = tc < thr;
                int y0 = full ? 0      : max(0, min(HH - 1, tminr - loose));
                int y1 = full ? HH - 1 : max(0, min(HH - 1, tmaxr + loose));
                int x0 = full ? 0      : max(0, min(WW - 1, tcmin - loose));
                int x1 = full ? WW - 1 : max(0, min(WW - 1, tcmax + loose));
                g_bbox[b] = make_int4(y0, y1, x0, x1);
                if (out_bbox) {
                    out_bbox[b * 4 + 0] = (float)y0;
                    out_bbox[b * 4 + 1] = (float)y1;
                    out_bbox[b * 4 + 2] = (float)x0;
                    out_bbox[b * 4 + 3] = (float)x1;
                }
                __threadfence();
                atomicExch(&g_flag[b], 1);     // release: bbox ready
            }
        }
        __syncthreads();    // also protects s_item reuse
    }

    // ---------------- Phase 2: fill (dynamic queue, per-sample gating) ----------------
    // Safe: on phase-2 entry the reduce queue is fully popped, and every popped
    // chunk is owned by an already-running CTA -> every flag WILL be set.
    for (;;) {
        if (t == 0) s_item = atomicAdd(&g_qfill, 1);
        __syncthreads();
        const int item = s_item;
        if (item >= NR) break;
        const int b  = item / RCH;
        const int ch = item - b * RCH;

        if (t == 0) {
            while (atomicAdd(&g_flag[b], 0) == 0) __nanosleep(64);
            __threadfence();   // acquire: order bbox read after flag
        }
        __syncthreads();

        const int4 bb = g_bbox[b];
        if (t < W4) {
            const int c = t * 4;
            float4 vin;
            vin.x = (c     >= bb.z && c     <= bb.w) ? 1.f : 0.f;
            vin.y = (c + 1 >= bb.z && c + 1 <= bb.w) ? 1.f : 0.f;
            vin.z = (c + 2 >= bb.z && c + 2 <= bb.w) ? 1.f : 0.f;
            vin.w = (c + 3 >= bb.z && c + 3 <= bb.w) ? 1.f : 0.f;
            const float4 vz = make_float4(0.f, 0.f, 0.f, 0.f);
            float4* p = out + (size_t)b * HW4 + (size_t)(ch * RPB) * W4 + t;
            const int r0 = ch * RPB;
            #pragma unroll 8
            for (int j = 0; j < RPB; j++) {
                const int r = r0 + j;
                st_stream(&p[(size_t)j * W4], (r >= bb.x && r <= bb.y) ? vin : vz, pstr);
            }
        }
        __syncthreads();    // protects s_item reuse
    }

    // ---------------- Exit: last block out resets all state ----------------
    if (t == 0) {
        if (atomicAdd(&g_exited, 1) == (int)gridDim.x - 1) {
            for (int i = 0; i < B; i++) { g_sdone[i] = 0; g_flag[i] = 0; }
            g_qred = 0; g_qfill = 0;
            __threadfence();
            g_exited = 0;
        }
    }
}

extern "C" void kernel_launch(void* const* d_in, const int* in_sizes, int n_in,
                              void* d_out, int out_size) {
    const float* mask = (const float*)d_in[0];
    const int* n_pts  = (const int*)d_in[1];
    const int* loose  = (const int*)d_in[2];
    float* out        = (float*)d_out;

    const int B = in_sizes[0] / HWX;
    const int att_elems = B * HWX;
    float* out_bbox = (out_size >= att_elems + 4 * B) ? (out + att_elems) : nullptr;

    ram_fused<<<GRID, NTHREADS>>>((const float4*)mask, n_pts, loose,
                                  (float4*)out, out_bbox, B);
}

// round 8
// speedup vs baseline: 1.1057x; 1.1057x over previous
#include <cuda_runtime.h>
#include <cstdint>

#define HH   480
#define WW   864
#define W4   216                 // WW/4
#define HW4  (HH*W4)             // 103680 float4 per sample
#define HWX  (HH*WW)
#define MAXB 224
#define RCH  15                  // reduce row-chunks per sample
#define RPB  32                  // rows per reduce block (480/15)
#define FROWS 8                  // rows per fill block
#define FBX  (HH/FROWS)          // 60

__device__ int      g_pcnt [MAXB][RCH];
__device__ int      g_pcmin[MAXB][RCH];
__device__ int      g_pcmax[MAXB][RCH];
__device__ unsigned g_prmask[MAXB][RCH];
__device__ int4     g_bbox[MAXB];
__device__ int      g_done = 0;   // self-resetting arrival counter

// L2 policy helpers.
__device__ __forceinline__ uint64_t pol_evict_last() {
    uint64_t p;
    asm("createpolicy.fractional.L2::evict_last.b64 %0, 1.0;" : "=l"(p));
    return p;
}
__device__ __forceinline__ float4 ld_pin(const float4* a, uint64_t pol) {
    float4 v;
    asm("ld.global.nc.L2::cache_hint.v4.f32 {%0,%1,%2,%3}, [%4], %5;"
        : "=f"(v.x), "=f"(v.y), "=f"(v.z), "=f"(v.w)
        : "l"(a), "l"(pol));
    return v;
}
// Write-through store: update DRAM during the fill window itself; leave no
// dirty L2 lines to spill writeback into the next reduce window, and don't
// displace the pinned mask.
__device__ __forceinline__ void st_wt(float4* a, float4 v) {
    asm volatile("st.global.wt.v4.f32 [%0], {%1,%2,%3,%4};"
                 :: "l"(a), "f"(v.x), "f"(v.y), "f"(v.z), "f"(v.w)
                 : "memory");
}

__global__ __launch_bounds__(224) void ram_reduce(const float4* __restrict__ mask,
                                                  const int* __restrict__ n_pts,
                                                  const int* __restrict__ n_loose,
                                                  float* __restrict__ out_bbox,
                                                  int B, int nblk)
{
    const int t   = threadIdx.x;          // column group (4 cols per thread)
    const int b   = blockIdx.y;
    const int ch  = blockIdx.x;
    const int row0 = ch * RPB;
    const uint64_t pol = pol_evict_last();

    float m0 = 0.f, m1 = 0.f, m2 = 0.f, m3 = 0.f;   // per-column running max
    int cnt = 0;
    unsigned rmask = 0;                              // fired-row bitmask (32 rows)

    if (t < W4) {
        const float4* p = mask + (size_t)b * HW4 + (size_t)row0 * W4 + t;
        #pragma unroll 8
        for (int j = 0; j < RPB; j++) {
            float4 v = ld_pin(&p[(size_t)j * W4], pol);  // keep mask L2-resident
            m0 = fmaxf(m0, v.x); m1 = fmaxf(m1, v.y);
            m2 = fmaxf(m2, v.z); m3 = fmaxf(m3, v.w);
            cnt += (v.x > 0.5f) + (v.y > 0.5f) + (v.z > 0.5f) + (v.w > 0.5f);
            float rm = fmaxf(fmaxf(v.x, v.y), fmaxf(v.z, v.w));
            rmask |= (rm > 0.5f) ? (1u << j) : 0u;
        }
    }

    const int c = t * 4;
    int cmin = (m0 > 0.5f) ? c
             : (m1 > 0.5f) ? c + 1
             : (m2 > 0.5f) ? c + 2
             : (m3 > 0.5f) ? c + 3 : (1 << 30);
    int cmax = (m3 > 0.5f) ? c + 3
             : (m2 > 0.5f) ? c + 2
             : (m1 > 0.5f) ? c + 1
             : (m0 > 0.5f) ? c : -1;

    cnt   = __reduce_add_sync(0xffffffffu, cnt);
    cmin  = __reduce_min_sync(0xffffffffu, cmin);
    cmax  = __reduce_max_sync(0xffffffffu, cmax);
    rmask = __reduce_or_sync (0xffffffffu, rmask);

    __shared__ int scnt[7], scmin[7], scmax[7];
    __shared__ unsigned srm[7];
    __shared__ int s_last;
    const int w = t >> 5;
    if ((t & 31) == 0) { scnt[w] = cnt; scmin[w] = cmin; scmax[w] = cmax; srm[w] = rmask; }
    __syncthreads();

    if (t == 0) {
        #pragma unroll
        for (int i = 1; i < 7; i++) {
            cnt += scnt[i];
            cmin = min(cmin, scmin[i]);
            cmax = max(cmax, scmax[i]);
            rmask |= srm[i];
        }
        g_pcnt[b][ch] = cnt; g_pcmin[b][ch] = cmin;
        g_pcmax[b][ch] = cmax; g_prmask[b][ch] = rmask;
        __threadfence();
        s_last = (atomicAdd(&g_done, 1) == nblk - 1) ? 1 : 0;
    }
    __syncthreads();

    if (s_last) {                       // last-arriving block finalizes everything
        __threadfence();                // acquire: make all partials visible
        if (t < B) {
            int tc = 0, tcmin = 1 << 30, tcmax = -1, tminr = 1 << 30, tmaxr = -1;
            #pragma unroll
            for (int i = 0; i < RCH; i++) {
                tc   += g_pcnt[t][i];
                tcmin = min(tcmin, g_pcmin[t][i]);
                tcmax = max(tcmax, g_pcmax[t][i]);
                unsigned rm = g_prmask[t][i];
                if (rm) {
                    tminr = min(tminr, i * RPB + (__ffs(rm) - 1));
                    tmaxr = max(tmaxr, i * RPB + (31 - __clz(rm)));
                }
            }
            const int loose = *n_loose, thr = *n_pts;
            const bool full = tc < thr;
            int y0 = full ? 0      : max(0, min(HH - 1, tminr - loose));
            int y1 = full ? HH - 1 : max(0, min(HH - 1, tmaxr + loose));
            int x0 = full ? 0      : max(0, min(WW - 1, tcmin - loose));
            int x1 = full ? WW - 1 : max(0, min(WW - 1, tcmax + loose));
            g_bbox[t] = make_int4(y0, y1, x0, x1);
            if (out_bbox) {
                out_bbox[t * 4 + 0] = (float)y0;
                out_bbox[t * 4 + 1] = (float)y1;
                out_bbox[t * 4 + 2] = (float)x0;
                out_bbox[t * 4 + 3] = (float)x1;
            }
        }
        if (t == 0) g_done = 0;         // reset for next graph replay
    }
}

__global__ __launch_bounds__(224) void ram_fill(float4* __restrict__ out)
{
    const int t = threadIdx.x;
    if (t >= W4) return;
    const int b  = blockIdx.y;
    const int r0 = blockIdx.x * FROWS;
    const int4 bb = g_bbox[b];

    const int c = t * 4;
    float4 vin;
    vin.x = (c     >= bb.z && c     <= bb.w) ? 1.f : 0.f;
    vin.y = (c + 1 >= bb.z && c + 1 <= bb.w) ? 1.f : 0.f;
    vin.z = (c + 2 >= bb.z && c + 2 <= bb.w) ? 1.f : 0.f;
    vin.w = (c + 3 >= bb.z && c + 3 <= bb.w) ? 1.f : 0.f;
    const float4 vz = make_float4(0.f, 0.f, 0.f, 0.f);

    float4* p = out + (size_t)b * HW4 + (size_t)r0 * W4 + t;
    #pragma unroll
    for (int j = 0; j < FROWS; j++) {
        const int r = r0 + j;
        st_wt(&p[(size_t)j * W4], (r >= bb.x && r <= bb.y) ? vin : vz);
    }
}

extern "C" void kernel_launch(void* const* d_in, const int* in_sizes, int n_in,
                              void* d_out, int out_size) {
    const float* mask = (const float*)d_in[0];
    const int* n_pts  = (const int*)d_in[1];
    const int* loose  = (const int*)d_in[2];
    float* out        = (float*)d_out;

    const int B = in_sizes[0] / HWX;
    const int att_elems = B * HWX;
    float* out_bbox = (out_size >= att_elems + 4 * B) ? (out + att_elems) : nullptr;

    ram_reduce<<<dim3(RCH, B), 224>>>((const float4*)mask, n_pts, loose,
                                      out_bbox, B, RCH * B);
    ram_fill<<<dim3(FBX, B), 224>>>((float4*)out);
}

// round 9
// speedup vs baseline: 1.8234x; 1.6491x over previous
#include <cuda_runtime.h>
#include <cstdint>

#define HH   480
#define WW   864
#define W4   216                 // WW/4
#define HW4  (HH*W4)             // 103680 float4 per sample
#define HWX  (HH*WW)
#define MAXB 224
#define FROWS 8                  // rows per fill block
#define FBX  (HH/FROWS)          // 60
#define NTA  256                 // bbox-search block size

__device__ int4 g_bbox[MAXB];

// ---------------------------------------------------------------------------
// Kernel A: per-sample early-exit bbox search. One block per sample.
// The four extremes are searches with early termination; the count check
// saturates at >= thr. Typical (non-degenerate) masks terminate after a few
// probes; pathological masks degrade to a full scan (still correct).
// ---------------------------------------------------------------------------
__global__ __launch_bounds__(NTA) void ram_bbox(const float4* __restrict__ mask,
                                                const int* __restrict__ n_pts,
                                                const int* __restrict__ n_loose,
                                                float* __restrict__ out_bbox,
                                                int B)
{
    const int t = threadIdx.x;
    const int b = blockIdx.x;
    const float4* base = mask + (size_t)b * HW4;
    const int thr   = *n_pts;
    const int loose = *n_loose;

    __shared__ int sh[8];
    __shared__ int s_val;

    // ---- Step 1: count with early-out at >= thr ----
    int total = 0;
    for (int start = 0; start < HW4; start += NTA) {
        const int idx = start + t;
        int c = 0;
        if (idx < HW4) {
            float4 v = base[idx];
            c = (v.x > 0.5f) + (v.y > 0.5f) + (v.z > 0.5f) + (v.w > 0.5f);
        }
        c = __reduce_add_sync(0xffffffffu, c);
        __syncthreads();                      // protect sh reuse
        if ((t & 31) == 0) sh[t >> 5] = c;
        __syncthreads();
        if (t == 0) {
            int s = 0;
            #pragma unroll
            for (int i = 0; i < 8; i++) s += sh[i];
            s_val = s;
        }
        __syncthreads();
        total += s_val;
        if (total >= thr) break;              // uniform break (all threads agree)
    }
    const bool full = (total < thr);

    int minr = HH, maxr = -1, minc = WW, maxc = -1;

    if (!full) {
        // ---- Step 2: min_r (top-down row probe) ----
        for (int r = 0; r < HH; r++) {
            bool hit = false;
            if (t < W4) {
                float4 v = base[(size_t)r * W4 + t];
                hit = (fmaxf(fmaxf(v.x, v.y), fmaxf(v.z, v.w)) > 0.5f);
            }
            if (__syncthreads_or((int)hit)) { minr = r; break; }
        }
        // ---- Step 3: max_r (bottom-up row probe) ----
        for (int r = HH - 1; r >= 0; r--) {
            bool hit = false;
            if (t < W4) {
                float4 v = base[(size_t)r * W4 + t];
                hit = (fmaxf(fmaxf(v.x, v.y), fmaxf(v.z, v.w)) > 0.5f);
            }
            if (__syncthreads_or((int)hit)) { maxr = r; break; }
        }
        // ---- Step 4: min_c (left-to-right float4-column probe) ----
        for (int cg = 0; cg < W4; cg++) {
            int lm = 1 << 30;
            for (int r = t; r < HH; r += NTA) {
                float4 v = base[(size_t)r * W4 + cg];
                int cm = (v.x > 0.5f) ? 4*cg
                       : (v.y > 0.5f) ? 4*cg + 1
                       : (v.z > 0.5f) ? 4*cg + 2
                       : (v.w > 0.5f) ? 4*cg + 3 : (1 << 30);
                lm = min(lm, cm);
            }
            lm = __reduce_min_sync(0xffffffffu, lm);
            __syncthreads();
            if ((t & 31) == 0) sh[t >> 5] = lm;
            __syncthreads();
            if (t == 0) {
                int s = sh[0];
                #pragma unroll
                for (int i = 1; i < 8; i++) s = min(s, sh[i]);
                s_val = s;
            }
            __syncthreads();
            if (s_val < (1 << 30)) { minc = s_val; break; }
        }
        // ---- Step 5: max_c (right-to-left float4-column probe) ----
        for (int cg = W4 - 1; cg >= 0; cg--) {
            int lm = -1;
            for (int r = t; r < HH; r += NTA) {
                float4 v = base[(size_t)r * W4 + cg];
                int cm = (v.w > 0.5f) ? 4*cg + 3
                       : (v.z > 0.5f) ? 4*cg + 2
                       : (v.y > 0.5f) ? 4*cg + 1
                       : (v.x > 0.5f) ? 4*cg : -1;
                lm = max(lm, cm);
            }
            lm = __reduce_max_sync(0xffffffffu, lm);
            __syncthreads();
            if ((t & 31) == 0) sh[t >> 5] = lm;
            __syncthreads();
            if (t == 0) {
                int s = sh[0];
                #pragma unroll
                for (int i = 1; i < 8; i++) s = max(s, sh[i]);
                s_val = s;
            }
            __syncthreads();
            if (s_val >= 0) { maxc = s_val; break; }
        }
    }

    if (t == 0) {
        int y0 = full ? 0      : max(0, min(HH - 1, minr - loose));
        int y1 = full ? HH - 1 : max(0, min(HH - 1, maxr + loose));
        int x0 = full ? 0      : max(0, min(WW - 1, minc - loose));
        int x1 = full ? WW - 1 : max(0, min(WW - 1, maxc + loose));
        g_bbox[b] = make_int4(y0, y1, x0, x1);
        if (out_bbox) {
            out_bbox[b * 4 + 0] = (float)y0;
            out_bbox[b * 4 + 1] = (float)y1;
            out_bbox[b * 4 + 2] = (float)x0;
            out_bbox[b * 4 + 3] = (float)x1;
        }
    }
}

// ---------------------------------------------------------------------------
// Kernel B: fill (unchanged structure; now the sole DRAM client).
// ---------------------------------------------------------------------------
__global__ __launch_bounds__(224) void ram_fill(float4* __restrict__ out)
{
    const int t = threadIdx.x;
    if (t >= W4) return;
    const int b  = blockIdx.y;
    const int r0 = blockIdx.x * FROWS;
    const int4 bb = g_bbox[b];

    const int c = t * 4;
    float4 vin;
    vin.x = (c     >= bb.z && c     <= bb.w) ? 1.f : 0.f;
    vin.y = (c + 1 >= bb.z && c + 1 <= bb.w) ? 1.f : 0.f;
    vin.z = (c + 2 >= bb.z && c + 2 <= bb.w) ? 1.f : 0.f;
    vin.w = (c + 3 >= bb.z && c + 3 <= bb.w) ? 1.f : 0.f;
    const float4 vz = make_float4(0.f, 0.f, 0.f, 0.f);

    float4* p = out + (size_t)b * HW4 + (size_t)r0 * W4 + t;
    #pragma unroll
    for (int j = 0; j < FROWS; j++) {
        const int r = r0 + j;
        p[(size_t)j * W4] = (r >= bb.x && r <= bb.y) ? vin : vz;
    }
}

extern "C" void kernel_launch(void* const* d_in, const int* in_sizes, int n_in,
                              void* d_out, int out_size) {
    const float* mask = (const float*)d_in[0];
    const int* n_pts  = (const int*)d_in[1];
    const int* loose  = (const int*)d_in[2];
    float* out        = (float*)d_out;

    const int B = in_sizes[0] / HWX;
    const int att_elems = B * HWX;
    float* out_bbox = (out_size >= att_elems + 4 * B) ? (out + att_elems) : nullptr;

    ram_bbox<<<B, NTA>>>((const float4*)mask, n_pts, loose, out_bbox, B);
    ram_fill<<<dim3(FBX, B), 224>>>((float4*)out);
}

// round 10
// speedup vs baseline: 1.9885x; 1.0906x over previous
#include <cuda_runtime.h>
#include <cstdint>

#define HH   480
#define WW   864
#define W4   216                 // WW/4
#define HW4  (HH*W4)             // 103680 float4 per sample
#define HWX  (HH*WW)
#define MAXB 224
#define FROWS 8                  // rows per fill block
#define FBX  (HH/FROWS)          // 60
#define NTA  256                 // bbox-search block size

// Raw search results, single-owner writes (always overwritten -> no reset).
__device__ int g_cnt [MAXB];
__device__ int g_minr[MAXB];
__device__ int g_maxr[MAXB];
__device__ int g_minc[MAXB];
__device__ int g_maxc[MAXB];

// ---------------------------------------------------------------------------
// Kernel A: grid (5, B). Each block runs ONE search task for one sample, so
// the five DRAM-latency round-trips run concurrently instead of serially.
// ---------------------------------------------------------------------------
__global__ __launch_bounds__(NTA) void ram_bbox(const float4* __restrict__ mask,
                                                const int* __restrict__ n_pts)
{
    const int t    = threadIdx.x;
    const int task = blockIdx.x;
    const int b    = blockIdx.y;
    const float4* base = mask + (size_t)b * HW4;

    __shared__ int sh[8];
    __shared__ int s_val;

    if (task == 0) {
        // ---- count with early-out at >= thr ----
        const int thr = *n_pts;
        int total = 0;
        for (int start = 0; start < HW4; start += NTA) {
            const int idx = start + t;
            int c = 0;
            if (idx < HW4) {
                float4 v = base[idx];
                c = (v.x > 0.5f) + (v.y > 0.5f) + (v.z > 0.5f) + (v.w > 0.5f);
            }
            c = __reduce_add_sync(0xffffffffu, c);
            __syncthreads();
            if ((t & 31) == 0) sh[t >> 5] = c;
            __syncthreads();
            if (t == 0) {
                int s = 0;
                #pragma unroll
                for (int i = 0; i < 8; i++) s += sh[i];
                s_val = s;
            }
            __syncthreads();
            total += s_val;
            if (total >= thr) break;          // uniform break
        }
        if (t == 0) g_cnt[b] = total;
    } else if (task == 1) {
        // ---- min_r: top-down row probe ----
        int res = HH;                          // sentinel (unused when full)
        for (int r = 0; r < HH; r++) {
            bool hit = false;
            if (t < W4) {
                float4 v = base[(size_t)r * W4 + t];
                hit = (fmaxf(fmaxf(v.x, v.y), fmaxf(v.z, v.w)) > 0.5f);
            }
            if (__syncthreads_or((int)hit)) { res = r; break; }
        }
        if (t == 0) g_minr[b] = res;
    } else if (task == 2) {
        // ---- max_r: bottom-up row probe ----
        int res = -1;
        for (int r = HH - 1; r >= 0; r--) {
            bool hit = false;
            if (t < W4) {
                float4 v = base[(size_t)r * W4 + t];
                hit = (fmaxf(fmaxf(v.x, v.y), fmaxf(v.z, v.w)) > 0.5f);
            }
            if (__syncthreads_or((int)hit)) { res = r; break; }
        }
        if (t == 0) g_maxr[b] = res;
    } else if (task == 3) {
        // ---- min_c: left-to-right float4-column probe ----
        int res = WW;
        for (int cg = 0; cg < W4; cg++) {
            int lm = 1 << 30;
            for (int r = t; r < HH; r += NTA) {
                float4 v = base[(size_t)r * W4 + cg];
                int cm = (v.x > 0.5f) ? 4*cg
                       : (v.y > 0.5f) ? 4*cg + 1
                       : (v.z > 0.5f) ? 4*cg + 2
                       : (v.w > 0.5f) ? 4*cg + 3 : (1 << 30);
                lm = min(lm, cm);
            }
            lm = __reduce_min_sync(0xffffffffu, lm);
            __syncthreads();
            if ((t & 31) == 0) sh[t >> 5] = lm;
            __syncthreads();
            if (t == 0) {
                int s = sh[0];
                #pragma unroll
                for (int i = 1; i < 8; i++) s = min(s, sh[i]);
                s_val = s;
            }
            __syncthreads();
            if (s_val < (1 << 30)) { res = s_val; break; }
        }
        if (t == 0) g_minc[b] = res;
    } else {
        // ---- max_c: right-to-left float4-column probe ----
        int res = -1;
        for (int cg = W4 - 1; cg >= 0; cg--) {
            int lm = -1;
            for (int r = t; r < HH; r += NTA) {
                float4 v = base[(size_t)r * W4 + cg];
                int cm = (v.w > 0.5f) ? 4*cg + 3
                       : (v.z > 0.5f) ? 4*cg + 2
                       : (v.y > 0.5f) ? 4*cg + 1
                       : (v.x > 0.5f) ? 4*cg : -1;
                lm = max(lm, cm);
            }
            lm = __reduce_max_sync(0xffffffffu, lm);
            __syncthreads();
            if ((t & 31) == 0) sh[t >> 5] = lm;
            __syncthreads();
            if (t == 0) {
                int s = sh[0];
                #pragma unroll
                for (int i = 1; i < 8; i++) s = max(s, sh[i]);
                s_val = s;
            }
            __syncthreads();
            if (s_val >= 0) { res = s_val; break; }
        }
        if (t == 0) g_maxc[b] = res;
    }
}

// ---------------------------------------------------------------------------
// Kernel B: fill. Finalizes the bbox inline (cheap, L2-hot) then streams out.
// ---------------------------------------------------------------------------
__global__ __launch_bounds__(224) void ram_fill(float4* __restrict__ out,
                                                const int* __restrict__ n_pts,
                                                const int* __restrict__ n_loose,
                                                float* __restrict__ out_bbox)
{
    const int t = threadIdx.x;
    const int b = blockIdx.y;

    __shared__ int4 sbb;
    if (t == 0) {
        const int thr = *n_pts, loose = *n_loose;
        const bool full = g_cnt[b] < thr;
        int y0 = full ? 0      : max(0, min(HH - 1, g_minr[b] - loose));
        int y1 = full ? HH - 1 : max(0, min(HH - 1, g_maxr[b] + loose));
        int x0 = full ? 0      : max(0, min(WW - 1, g_minc[b] - loose));
        int x1 = full ? WW - 1 : max(0, min(WW - 1, g_maxc[b] + loose));
        sbb = make_int4(y0, y1, x0, x1);
        if (out_bbox && blockIdx.x == 0) {
            out_bbox[b * 4 + 0] = (float)y0;
            out_bbox[b * 4 + 1] = (float)y1;
            out_bbox[b * 4 + 2] = (float)x0;
            out_bbox[b * 4 + 3] = (float)x1;
        }
    }
    __syncthreads();
    if (t >= W4) return;

    const int4 bb = sbb;
    const int r0 = blockIdx.x * FROWS;
    const int c = t * 4;
    float4 vin;
    vin.x = (c     >= bb.z && c     <= bb.w) ? 1.f : 0.f;
    vin.y = (c + 1 >= bb.z && c + 1 <= bb.w) ? 1.f : 0.f;
    vin.z = (c + 2 >= bb.z && c + 2 <= bb.w) ? 1.f : 0.f;
    vin.w = (c + 3 >= bb.z && c + 3 <= bb.w) ? 1.f : 0.f;
    const float4 vz = make_float4(0.f, 0.f, 0.f, 0.f);

    float4* p = out + (size_t)b * HW4 + (size_t)r0 * W4 + t;
    #pragma unroll
    for (int j = 0; j < FROWS; j++) {
        const int r = r0 + j;
        p[(size_t)j * W4] = (r >= bb.x && r <= bb.y) ? vin : vz;
    }
}

extern "C" void kernel_launch(void* const* d_in, const int* in_sizes, int n_in,
                              void* d_out, int out_size) {
    const float* mask = (const float*)d_in[0];
    const int* n_pts  = (const int*)d_in[1];
    const int* loose  = (const int*)d_in[2];
    float* out        = (float*)d_out;

    const int B = in_sizes[0] / HWX;
    const int att_elems = B * HWX;
    float* out_bbox = (out_size >= att_elems + 4 * B) ? (out + att_elems) : nullptr;

    ram_bbox<<<dim3(5, B), NTA>>>((const float4*)mask, n_pts);
    ram_fill<<<dim3(FBX, B), 224>>>((float4*)out, n_pts, loose, out_bbox);
}